// round 6
// baseline (speedup 1.0000x reference)
#include <cuda_runtime.h>

// Decoder_predict: batched greedy goals-NMS.  B=256, N=4096, T=30, K=6.
// scores = class * centerness, thr^2 = 4.0.
//
// V6: single fused kernel, 4 CTAs per batch (1024 CTAs x 256 thr) for CTA-level
// latency hiding, with a "last CTA finishes the batch" pattern.
//  Phase 1 (all CTAs): each thread loads 4 candidates with exactly four
//    float4 loads; each warp reduces its 128 candidates to a top-6 by score;
//    48 survivors per CTA -> __device__ scratch (192 per batch).
//  Phase 2 (last CTA of each batch, via per-batch atomic counter): warp 0
//    pulls the 192 survivors from L2 (__ldcg, 6/lane) and runs the 6 greedy
//    NMS rounds with shuffles only; then 256 threads gather trajectories.
// Packed key (score_bits<<32)|~idx : scores >= 0 so float bits are
// order-monotone; ~idx = lower-original-index tie-break (matches stable
// argsort); key is never 0 for a real candidate.

#define NMS_B 256
#define NMS_N 4096
#define NMS_T 30
#define NMS_K 6
#define NMS_THR2 4.0f
#define THREADS 256
#define CTAS_PER_B 4
#define CHUNK (NMS_N / CTAS_PER_B)          // 1024 candidates per CTA
#define SURV_PER_CTA 48                      // 8 warps * 6
#define SURV_PER_B (CTAS_PER_B * SURV_PER_CTA)  // 192

__device__ float4       g_surv[NMS_B * SURV_PER_B];  // x, y, score, ~idx bits
__device__ unsigned int g_cnt[NMS_B];                 // monotone; used mod 4

static __device__ __forceinline__ unsigned long long pack_key(float s, unsigned idx) {
    return ((unsigned long long)__float_as_uint(s) << 32) | (unsigned)(~idx);
}

__global__ __launch_bounds__(THREADS)
void nms_fused_kernel(const float* __restrict__ coord,   // [B,1,N,2]
                      const float* __restrict__ cls,     // [B,1,N]
                      const float* __restrict__ traj,    // [B,1,N,T,2]
                      const float* __restrict__ cent,    // [B,1,N]
                      float* __restrict__ out)
{
    const int blk  = blockIdx.x;
    const int b    = blk >> 2;
    const int q    = blk & 3;                 // quarter of the batch
    const int tid  = threadIdx.x;
    const int wid  = tid >> 5;
    const int lane = tid & 31;

    // ---- Phase 1: load 4 candidates/thread with 4x float4, warp top-6. ----
    {
        const float4* c4 = (const float4*)(coord + (size_t)b * NMS_N * 2 + q * CHUNK * 2);
        const float4* s4 = (const float4*)(cls   + (size_t)b * NMS_N + q * CHUNK);
        const float4* e4 = (const float4*)(cent  + (size_t)b * NMS_N + q * CHUNK);

        const float4 ca = c4[2 * tid];        // cands 4t, 4t+1
        const float4 cb = c4[2 * tid + 1];    // cands 4t+2, 4t+3
        const float4 sv = s4[tid];
        const float4 ev = e4[tid];

        const unsigned n0 = (unsigned)(q * CHUNK + 4 * tid);
        float x[4] = {ca.x, ca.z, cb.x, cb.z};
        float y[4] = {ca.y, ca.w, cb.y, cb.w};
        unsigned long long pk[4];
        pk[0] = pack_key(sv.x * ev.x, n0);
        pk[1] = pack_key(sv.y * ev.y, n0 + 1u);
        pk[2] = pack_key(sv.z * ev.z, n0 + 2u);
        pk[3] = pack_key(sv.w * ev.w, n0 + 3u);

        float4* dst = g_surv + (size_t)blk * SURV_PER_CTA + wid * NMS_K;
#pragma unroll
        for (int r = 0; r < NMS_K; r++) {
            unsigned long long tmax = max(max(pk[0], pk[1]), max(pk[2], pk[3]));
            unsigned long long m = tmax;
#pragma unroll
            for (int off = 16; off > 0; off >>= 1)
                m = max(m, __shfl_xor_sync(0xFFFFFFFFu, m, off));
            if (tmax == m) {                  // keys unique -> exactly one lane
                float wx = 0.f, wy = 0.f;
#pragma unroll
                for (int j = 0; j < 4; j++)
                    if (pk[j] == m) { wx = x[j]; wy = y[j]; pk[j] = 0ULL; }
                dst[r] = make_float4(
                    wx, wy,
                    __uint_as_float((unsigned)(m >> 32)),
                    __uint_as_float((unsigned)(m & 0xFFFFFFFFu)));
            }
        }
    }

    // ---- Arrival protocol: last CTA of the batch finishes it. ----
    __threadfence();               // release our survivor writes
    __syncthreads();
    __shared__ unsigned s_old;
    if (tid == 0) s_old = atomicAdd(&g_cnt[b], 1u);
    __syncthreads();
    if ((s_old & 3u) != 3u) return;   // not the last quarter -> done

    __threadfence();               // acquire side before reading peers' data

    __shared__ float sel_x[NMS_K], sel_y[NMS_K], sel_s[NMS_K];
    __shared__ int   sel_i[NMS_K];

    // ---- Phase 2: warp 0 greedy NMS over 192 survivors (6 per lane). ----
    if (wid == 0) {
        float  vx[6], vy[6];
        unsigned long long vp[6];
        const float4* sp = g_surv + (size_t)b * SURV_PER_B;
#pragma unroll
        for (int h = 0; h < 6; h++) {
            const float4 v = __ldcg(&sp[lane + 32 * h]);   // L2, skip stale L1
            vx[h] = v.x;  vy[h] = v.y;
            vp[h] = ((unsigned long long)__float_as_uint(v.z) << 32)
                  | (unsigned)__float_as_uint(v.w);
        }
#pragma unroll
        for (int r = 0; r < NMS_K; r++) {
            unsigned long long tmax = vp[0];
#pragma unroll
            for (int h = 1; h < 6; h++) tmax = max(tmax, vp[h]);
            unsigned long long m = tmax;
#pragma unroll
            for (int off = 16; off > 0; off >>= 1)
                m = max(m, __shfl_xor_sync(0xFFFFFFFFu, m, off));

            if (m == 0ULL) {
                if (lane == 0) {
                    sel_i[r] = -1; sel_s[r] = 0.0f;
                    sel_x[r] = 0.0f; sel_y[r] = 0.0f;
                }
            } else {
                int hm = -1;
#pragma unroll
                for (int h = 0; h < 6; h++)
                    if (vp[h] == m) hm = h;
                const unsigned bal = __ballot_sync(0xFFFFFFFFu, hm >= 0);
                const int wl = __ffs(bal) - 1;
                float fx = 0.f, fy = 0.f;
#pragma unroll
                for (int h = 0; h < 6; h++)
                    if (h == hm) { fx = vx[h]; fy = vy[h]; }
                const float px = __shfl_sync(0xFFFFFFFFu, fx, wl);
                const float py = __shfl_sync(0xFFFFFFFFu, fy, wl);
                if (lane == wl) {
                    sel_x[r] = px;  sel_y[r] = py;
                    sel_s[r] = __uint_as_float((unsigned)(m >> 32));
                    sel_i[r] = (int)(~(unsigned)(m & 0xFFFFFFFFu));
                }
                // Suppress survivors within thr (incl. the winner itself).
#pragma unroll
                for (int h = 0; h < 6; h++) {
                    const float dx = vx[h] - px;
                    const float dy = vy[h] - py;
                    if (dx * dx + dy * dy < NMS_THR2) vp[h] = 0ULL;
                }
            }
        }
    }
    __syncthreads();

    // ---- Phase 3: outputs. pred_trajs [B,K,T,2] | probs [B,K] | goals [B,K,2]
    float* out_traj = out;
    float* out_prob = out + (size_t)NMS_B * NMS_K * NMS_T * 2;
    float* out_goal = out_prob + (size_t)NMS_B * NMS_K;

    if (tid < NMS_K) {
        const int  k     = tid;
        const bool valid = (sel_i[k] >= 0);
        // Fallback slot: sel_idx stays 0 -> round-0 point's score/traj,
        // goal stays (0,0).
        out_prob[(size_t)b * NMS_K + k]           = valid ? sel_s[k] : sel_s[0];
        out_goal[((size_t)b * NMS_K + k) * 2 + 0] = valid ? sel_x[k] : 0.0f;
        out_goal[((size_t)b * NMS_K + k) * 2 + 1] = valid ? sel_y[k] : 0.0f;
    }

    // Traj gather: 6 rows * 15 float4 = 90 float4 per batch.
    if (tid < NMS_K * 15) {
        const int k = tid / 15;
        const int p = tid % 15;
        const int src = (sel_i[k] >= 0) ? sel_i[k] : sel_i[0];
        ((float4*)out_traj)[((size_t)b * NMS_K + k) * 15 + p] =
            ((const float4*)traj)[((size_t)b * NMS_N + src) * 15 + p];
    }
}

extern "C" void kernel_launch(void* const* d_in, const int* in_sizes, int n_in,
                              void* d_out, int out_size) {
    const float* coord = (const float*)d_in[0];  // outputs_coord     [B,1,N,2]
    const float* cls   = (const float*)d_in[1];  // outputs_class     [B,1,N]
    const float* traj  = (const float*)d_in[2];  // outputs_traj      [B,1,N,T,2]
    const float* cent  = (const float*)d_in[3];  // outputs_centerness[B,1,N]
    float* out = (float*)d_out;

    nms_fused_kernel<<<NMS_B * CTAS_PER_B, THREADS>>>(coord, cls, traj, cent, out);
}

// round 7
// speedup vs baseline: 1.4048x; 1.4048x over previous
#include <cuda_runtime.h>

// Decoder_predict: batched greedy goals-NMS.  B=256, N=4096, T=30, K=6.
// scores = class * centerness, thr^2 = 4.0.
//
// V7: byte-diet. Phase 1 reads ONLY the score inputs (cls, cent: 8 MB total);
// coordinates are gathered later for just the ~96 survivors. All measured
// variants were pinned at ~1.35 TB/s effective, so halving bytes ~halves time.
//  Phase 1: 512 thr/CTA, 8 cands/thread (2x float4 cls + 2x float4 cent).
//           Per-warp top-6 by packed key (score_bits<<32)|~idx  -> smem (u64).
//  Phase 2: warp 0 gathers 96 survivor coords (float2) and runs the 6 greedy
//           NMS rounds with shuffles only.
//  Phase 3: float4 trajectory gather (rows are 240 B = 15 float4).
// Keys: scores >= 0 so float bits are order-monotone; ~idx gives
// lower-original-index tie-break (matches stable argsort); never 0 for a
// real candidate.

#define NMS_B 256
#define NMS_N 4096
#define NMS_T 30
#define NMS_K 6
#define NMS_THR2 4.0f
#define THREADS 512
#define WARPS (THREADS / 32)        // 16
#define SURV (WARPS * NMS_K)        // 96

static __device__ __forceinline__ unsigned long long pack_key(float s, unsigned idx) {
    return ((unsigned long long)__float_as_uint(s) << 32) | (unsigned)(~idx);
}

__global__ __launch_bounds__(THREADS, 2)
void nms_goals_kernel(const float* __restrict__ coord,   // [B,1,N,2]
                      const float* __restrict__ cls,     // [B,1,N]
                      const float* __restrict__ traj,    // [B,1,N,T,2]
                      const float* __restrict__ cent,    // [B,1,N]
                      float* __restrict__ out)
{
    const int b    = blockIdx.x;
    const int tid  = threadIdx.x;
    const int wid  = tid >> 5;
    const int lane = tid & 31;

    // ---- Phase 1: scores only. 8 candidates/thread. ----
    const float4* s4 = (const float4*)(cls  + (size_t)b * NMS_N);
    const float4* e4 = (const float4*)(cent + (size_t)b * NMS_N);

    unsigned long long pk[8];
    {
        const float4 sa = s4[tid];
        const float4 sb = s4[tid + THREADS];
        const float4 ea = e4[tid];
        const float4 eb = e4[tid + THREADS];
        const unsigned i0 = 4u * (unsigned)tid;
        const unsigned i1 = 4u * (unsigned)(tid + THREADS);
        pk[0] = pack_key(sa.x * ea.x, i0);
        pk[1] = pack_key(sa.y * ea.y, i0 + 1u);
        pk[2] = pack_key(sa.z * ea.z, i0 + 2u);
        pk[3] = pack_key(sa.w * ea.w, i0 + 3u);
        pk[4] = pack_key(sb.x * eb.x, i1);
        pk[5] = pack_key(sb.y * eb.y, i1 + 1u);
        pk[6] = pack_key(sb.z * eb.z, i1 + 2u);
        pk[7] = pack_key(sb.w * eb.w, i1 + 3u);
    }

    __shared__ unsigned long long surv[SURV];
    __shared__ float sel_x[NMS_K], sel_y[NMS_K], sel_s[NMS_K];
    __shared__ int   sel_i[NMS_K];

    {
        // Thread-local max computed once; only the winning lane refreshes.
        unsigned long long tmax = pk[0];
#pragma unroll
        for (int j = 1; j < 8; j++) tmax = max(tmax, pk[j]);

#pragma unroll
        for (int r = 0; r < NMS_K; r++) {
            unsigned long long m = tmax;
#pragma unroll
            for (int off = 16; off > 0; off >>= 1)
                m = max(m, __shfl_xor_sync(0xFFFFFFFFu, m, off));
            if (tmax == m) {                 // unique keys -> exactly one lane
                surv[wid * NMS_K + r] = m;
#pragma unroll
                for (int j = 0; j < 8; j++) if (pk[j] == m) pk[j] = 0ULL;
                tmax = pk[0];
#pragma unroll
                for (int j = 1; j < 8; j++) tmax = max(tmax, pk[j]);
            }
        }
    }
    __syncthreads();

    // ---- Phase 2: gather survivor coords, greedy NMS (warp 0, 3/lane). ----
    if (wid == 0) {
        const float2* cptr = (const float2*)(coord + (size_t)b * NMS_N * 2);
        unsigned long long vp[3];
        float vx[3], vy[3];
        int vidx[3];
#pragma unroll
        for (int h = 0; h < 3; h++) {
            vp[h]   = surv[lane + 32 * h];
            vidx[h] = (int)(~(unsigned)(vp[h] & 0xFFFFFFFFu));
        }
        float2 cv[3];
#pragma unroll
        for (int h = 0; h < 3; h++) cv[h] = cptr[vidx[h]];   // 96 x 8B gather
#pragma unroll
        for (int h = 0; h < 3; h++) { vx[h] = cv[h].x; vy[h] = cv[h].y; }

#pragma unroll
        for (int r = 0; r < NMS_K; r++) {
            unsigned long long m = max(max(vp[0], vp[1]), vp[2]);
#pragma unroll
            for (int off = 16; off > 0; off >>= 1)
                m = max(m, __shfl_xor_sync(0xFFFFFFFFu, m, off));

            if (m == 0ULL) {
                if (lane == 0) {
                    sel_i[r] = -1; sel_s[r] = 0.0f;
                    sel_x[r] = 0.0f; sel_y[r] = 0.0f;
                }
            } else {
                int hm = -1;
#pragma unroll
                for (int h = 0; h < 3; h++) if (vp[h] == m) hm = h;
                const unsigned bal = __ballot_sync(0xFFFFFFFFu, hm >= 0);
                const int wl = __ffs(bal) - 1;
                float fx = 0.f, fy = 0.f;
#pragma unroll
                for (int h = 0; h < 3; h++) if (h == hm) { fx = vx[h]; fy = vy[h]; }
                const float px = __shfl_sync(0xFFFFFFFFu, fx, wl);
                const float py = __shfl_sync(0xFFFFFFFFu, fy, wl);
                if (lane == wl) {
                    sel_x[r] = px;  sel_y[r] = py;
                    sel_s[r] = __uint_as_float((unsigned)(m >> 32));
                    sel_i[r] = (int)(~(unsigned)(m & 0xFFFFFFFFu));
                }
                // Suppress survivors within thr (incl. the winner itself).
#pragma unroll
                for (int h = 0; h < 3; h++) {
                    const float dx = vx[h] - px;
                    const float dy = vy[h] - py;
                    if (dx * dx + dy * dy < NMS_THR2) vp[h] = 0ULL;
                }
            }
        }
    }
    __syncthreads();

    // ---- Phase 3: outputs. pred_trajs [B,K,T,2] | probs [B,K] | goals [B,K,2]
    float* out_traj = out;
    float* out_prob = out + (size_t)NMS_B * NMS_K * NMS_T * 2;
    float* out_goal = out_prob + (size_t)NMS_B * NMS_K;

    if (tid < NMS_K) {
        const int  k     = tid;
        const bool valid = (sel_i[k] >= 0);
        // Fallback slot: sel_idx stays 0 -> round-0 point's score/traj,
        // goal stays (0,0).
        out_prob[(size_t)b * NMS_K + k]           = valid ? sel_s[k] : sel_s[0];
        out_goal[((size_t)b * NMS_K + k) * 2 + 0] = valid ? sel_x[k] : 0.0f;
        out_goal[((size_t)b * NMS_K + k) * 2 + 1] = valid ? sel_y[k] : 0.0f;
    }

    // Traj gather: 6 rows * 15 float4 = 90 float4 per batch.
    if (tid < NMS_K * 15) {
        const int k = tid / 15;
        const int p = tid % 15;
        const int src = (sel_i[k] >= 0) ? sel_i[k] : sel_i[0];
        ((float4*)out_traj)[((size_t)b * NMS_K + k) * 15 + p] =
            ((const float4*)traj)[((size_t)b * NMS_N + src) * 15 + p];
    }
}

extern "C" void kernel_launch(void* const* d_in, const int* in_sizes, int n_in,
                              void* d_out, int out_size) {
    const float* coord = (const float*)d_in[0];  // outputs_coord     [B,1,N,2]
    const float* cls   = (const float*)d_in[1];  // outputs_class     [B,1,N]
    const float* traj  = (const float*)d_in[2];  // outputs_traj      [B,1,N,T,2]
    const float* cent  = (const float*)d_in[3];  // outputs_centerness[B,1,N]
    float* out = (float*)d_out;

    nms_goals_kernel<<<NMS_B, THREADS>>>(coord, cls, traj, cent, out);
}